// round 14
// baseline (speedup 1.0000x reference)
#include <cuda_runtime.h>
#include <math.h>

// ---------------------------------------------------------------------------
// SelfExpandingGate: N=500000 rows, 40 floats in/out.
// TPB=64, 2 rows/thread (rows t and t+64 of a 128-row tile).
// Quadratic contraction: TWO fully-unrolled straight-line passes of 12 outputs
// (only 6 ull accs per row live at a time) over all 172 features; weights
// amortized across both rows. Gated bilinear: both rows per w-pair.
// All heavy FMAs are packed fp32x2. I/O staged coalesced through SMEM.
// NO rolled loops over array state, NO occupancy caps (spill-safe).
// ---------------------------------------------------------------------------

#define NFEAT 172
#define TPB   64
#define RPB   128          // rows per block
#define RP    44           // padded slot stride (floats), conflict-free LDS.128

__device__ float g_WqLo[NFEAT * 12];      // quadratic weights, outputs 0-11
__device__ float g_WqHi[NFEAT * 12];      // outputs 12-23 (12-15 scal, 16-23 gates)
__device__ float g_WgP[4 * 16 * 8 * 2];   // [wp][u][b][lane], w = wp*2+lane

typedef unsigned long long ull;

__device__ __forceinline__ ull pk2s(float f) {
    ull r; asm("mov.b64 %0,{%1,%1};" : "=l"(r) : "f"(f)); return r;
}
__device__ __forceinline__ void upk2(ull v, float& lo, float& hi) {
    asm("mov.b64 {%0,%1},%2;" : "=f"(lo), "=f"(hi) : "l"(v));
}
__device__ __forceinline__ ull fma2(ull a, ull b, ull c) {
    ull d; asm("fma.rn.f32x2 %0,%1,%2,%3;" : "=l"(d) : "l"(a), "l"(b), "l"(c)); return d;
}
__device__ __forceinline__ float sigf(float x) {
    return __fdividef(1.0f, 1.0f + __expf(-x));
}

// One full feature sweep accumulating 12 outputs (3 ulonglong2 per feature)
// for both rows. Expanded inline; wb must be a compile-time-selected pointer.
#define QUAD_PASS(wb, accA, accB)                                              \
    {                                                                          \
        int k = 0;                                                             \
        _Pragma("unroll")                                                      \
        for (int u = 0; u < 16; u++) {                                         \
            _Pragma("unroll")                                                  \
            for (int vv = u; vv < 16; vv++) {                                  \
                ull fA2 = pk2s(sA[u] * sA[vv]);                                \
                ull fB2 = pk2s(sB[u] * sB[vv]);                                \
                const ulonglong2* w =                                          \
                    reinterpret_cast<const ulonglong2*>((wb) + k * 12);        \
                ulonglong2 w0 = w[0];                                          \
                accA[0] = fma2(fA2, w0.x, accA[0]);                            \
                accA[1] = fma2(fA2, w0.y, accA[1]);                            \
                accB[0] = fma2(fB2, w0.x, accB[0]);                            \
                accB[1] = fma2(fB2, w0.y, accB[1]);                            \
                ulonglong2 w1 = w[1];                                          \
                accA[2] = fma2(fA2, w1.x, accA[2]);                            \
                accA[3] = fma2(fA2, w1.y, accA[3]);                            \
                accB[2] = fma2(fB2, w1.x, accB[2]);                            \
                accB[3] = fma2(fB2, w1.y, accB[3]);                            \
                ulonglong2 w2 = w[2];                                          \
                accA[4] = fma2(fA2, w2.x, accA[4]);                            \
                accA[5] = fma2(fA2, w2.y, accA[5]);                            \
                accB[4] = fma2(fB2, w2.x, accB[4]);                            \
                accB[5] = fma2(fB2, w2.y, accB[5]);                            \
                k++;                                                           \
            }                                                                  \
        }                                                                      \
        _Pragma("unroll")                                                      \
        for (int a = 0; a < 8; a++) {                                          \
            _Pragma("unroll")                                                  \
            for (int b = a; b < 8; b++) {                                      \
                float fA = vA[a*3+0]*vA[b*3+0] + vA[a*3+1]*vA[b*3+1]           \
                         + vA[a*3+2]*vA[b*3+2];                                \
                float fB = vB[a*3+0]*vB[b*3+0] + vB[a*3+1]*vB[b*3+1]           \
                         + vB[a*3+2]*vB[b*3+2];                                \
                ull fA2 = pk2s(fA);                                            \
                ull fB2 = pk2s(fB);                                            \
                const ulonglong2* w =                                          \
                    reinterpret_cast<const ulonglong2*>((wb) + k * 12);        \
                ulonglong2 w0 = w[0];                                          \
                accA[0] = fma2(fA2, w0.x, accA[0]);                            \
                accA[1] = fma2(fA2, w0.y, accA[1]);                            \
                accB[0] = fma2(fB2, w0.x, accB[0]);                            \
                accB[1] = fma2(fB2, w0.y, accB[1]);                            \
                ulonglong2 w1 = w[1];                                          \
                accA[2] = fma2(fA2, w1.x, accA[2]);                            \
                accA[3] = fma2(fA2, w1.y, accA[3]);                            \
                accB[2] = fma2(fB2, w1.x, accB[2]);                            \
                accB[3] = fma2(fB2, w1.y, accB[3]);                            \
                ulonglong2 w2 = w[2];                                          \
                accA[4] = fma2(fA2, w2.x, accA[4]);                            \
                accA[5] = fma2(fA2, w2.y, accA[5]);                            \
                accB[4] = fma2(fB2, w2.x, accB[4]);                            \
                accB[5] = fma2(fB2, w2.y, accB[5]);                            \
                k++;                                                           \
            }                                                                  \
        }                                                                      \
    }

// ---------------------------------------------------------------------------
// Prep: build combined weights. One block (tiny).
// ---------------------------------------------------------------------------
__global__ void prep_kernel(const float* __restrict__ Wss0,
                            const float* __restrict__ Wvv0,
                            const float* __restrict__ Wss1,
                            const float* __restrict__ Wvv1,
                            const float* __restrict__ Wsv,
                            const float* __restrict__ Wvs) {
    const float CSC  = 0.055901699437494740f;          // 1/sqrt(320)
    const float CSC3 = CSC * 0.57735026918962576f;     // CSC / sqrt(3)
    int tid = threadIdx.x;

    for (int l = tid; l < NFEAT * 24; l += blockDim.x) {
        int kk = l / 24, j = l % 24;
        float val;
        if (kk < 136) {                     // ss pair feature
            int u = 0, r = kk;
            while (r >= 16 - u) { r -= 16 - u; u++; }
            int v = u + r;
            if (j < 16) {
                val = Wss0[(u * 16 + v) * 16 + j];
                if (u != v) val += Wss0[(v * 16 + u) * 16 + j];
            } else {
                int w = j - 16;
                val = Wss1[(u * 16 + v) * 8 + w];
                if (u != v) val += Wss1[(v * 16 + u) * 8 + w];
            }
            val *= CSC;
        } else {                            // vv pair feature
            int kv = kk - 136;
            int a = 0, r = kv;
            while (r >= 8 - a) { r -= 8 - a; a++; }
            int b = a + r;
            if (j < 16) {
                val = Wvv0[(a * 8 + b) * 16 + j];
                if (a != b) val += Wvv0[(b * 8 + a) * 16 + j];
            } else {
                int w = j - 16;
                val = Wvv1[(a * 8 + b) * 8 + w];
                if (a != b) val += Wvv1[(b * 8 + a) * 8 + w];
            }
            val *= CSC3;
        }
        if (j < 12) g_WqLo[kk * 12 + j] = val;
        else        g_WqHi[kk * 12 + (j - 12)] = val;
    }
    // gated weights: [wp][u][b][lane], w = wp*2 + lane
    for (int l = tid; l < 4 * 16 * 8 * 2; l += blockDim.x) {
        int lane = l & 1;
        int b = (l >> 1) & 7;
        int u = (l >> 4) & 15;
        int wp = l >> 8;
        int w = wp * 2 + lane;
        g_WgP[l] = (Wsv[(u * 8 + b) * 8 + w] + Wvs[(b * 16 + u) * 8 + w]) * 0.0625f;
    }
}

// ---------------------------------------------------------------------------
// Main kernel.
// ---------------------------------------------------------------------------
__global__ void __launch_bounds__(TPB)
seg_kernel(const float* __restrict__ x, float* __restrict__ out,
           int nrows, float silu_c, float sig_c) {
    __shared__ __align__(16) float sWqLo[NFEAT * 12];    // 8.25 KB
    __shared__ __align__(16) float sWqHi[NFEAT * 12];    // 8.25 KB
    __shared__ __align__(16) float sWgP[4 * 16 * 8 * 2]; // 4 KB
    __shared__ __align__(16) float sbuf[RPB * RP];       // 22.5 KB

    const int tid = threadIdx.x;
    for (int i = tid; i < NFEAT * 12; i += TPB) { sWqLo[i] = g_WqLo[i]; sWqHi[i] = g_WqHi[i]; }
    for (int i = tid; i < 4 * 16 * 8 * 2; i += TPB) sWgP[i] = g_WgP[i];

    const int base = blockIdx.x * RPB;
    int rows = nrows - base; if (rows > RPB) rows = RPB;
    const int n4 = rows * 10;

    // ---- stage inputs coalesced into padded SMEM ----
    const float4* gx = reinterpret_cast<const float4*>(x + (size_t)base * 40);
    for (int j = tid; j < n4; j += TPB) {
        float4 t = gx[j];
        *reinterpret_cast<float4*>(&sbuf[(j / 10) * RP + (j % 10) * 4]) = t;
    }
    __syncthreads();

    const bool validA = tid < rows;
    const bool validB = (tid + TPB) < rows;
    float* slotA = &sbuf[tid * RP];
    float* slotB = &sbuf[(tid + TPB) * RP];

    // ---- pull both rows into registers (conflict-free LDS.128) ----
    float sA[16], vA[24], sB[16], vB[24];
    {
        const float4* r4 = reinterpret_cast<const float4*>(slotA);
        float4 t;
        t = r4[0]; sA[0]=t.x; sA[1]=t.y; sA[2]=t.z; sA[3]=t.w;
        t = r4[1]; sA[4]=t.x; sA[5]=t.y; sA[6]=t.z; sA[7]=t.w;
        t = r4[2]; sA[8]=t.x; sA[9]=t.y; sA[10]=t.z; sA[11]=t.w;
        t = r4[3]; sA[12]=t.x; sA[13]=t.y; sA[14]=t.z; sA[15]=t.w;
        t = r4[4]; vA[0]=t.x; vA[1]=t.y; vA[2]=t.z; vA[3]=t.w;
        t = r4[5]; vA[4]=t.x; vA[5]=t.y; vA[6]=t.z; vA[7]=t.w;
        t = r4[6]; vA[8]=t.x; vA[9]=t.y; vA[10]=t.z; vA[11]=t.w;
        t = r4[7]; vA[12]=t.x; vA[13]=t.y; vA[14]=t.z; vA[15]=t.w;
        t = r4[8]; vA[16]=t.x; vA[17]=t.y; vA[18]=t.z; vA[19]=t.w;
        t = r4[9]; vA[20]=t.x; vA[21]=t.y; vA[22]=t.z; vA[23]=t.w;
    }
    {
        const float4* r4 = reinterpret_cast<const float4*>(slotB);
        float4 t;
        t = r4[0]; sB[0]=t.x; sB[1]=t.y; sB[2]=t.z; sB[3]=t.w;
        t = r4[1]; sB[4]=t.x; sB[5]=t.y; sB[6]=t.z; sB[7]=t.w;
        t = r4[2]; sB[8]=t.x; sB[9]=t.y; sB[10]=t.z; sB[11]=t.w;
        t = r4[3]; sB[12]=t.x; sB[13]=t.y; sB[14]=t.z; sB[15]=t.w;
        t = r4[4]; vB[0]=t.x; vB[1]=t.y; vB[2]=t.z; vB[3]=t.w;
        t = r4[5]; vB[4]=t.x; vB[5]=t.y; vB[6]=t.z; vB[7]=t.w;
        t = r4[6]; vB[8]=t.x; vB[9]=t.y; vB[10]=t.z; vB[11]=t.w;
        t = r4[7]; vB[12]=t.x; vB[13]=t.y; vB[14]=t.z; vB[15]=t.w;
        t = r4[8]; vB[16]=t.x; vB[17]=t.y; vB[18]=t.z; vB[19]=t.w;
        t = r4[9]; vB[20]=t.x; vB[21]=t.y; vB[22]=t.z; vB[23]=t.w;
    }
    // No barrier: each slot touched only by its owner until the final flush.

    // ================= quadratic pass 1: outputs 0-11 =================
    {
        ull accA[6], accB[6];
        #pragma unroll
        for (int j = 0; j < 6; j++) { accA[j] = 0ull; accB[j] = 0ull; }

        QUAD_PASS(sWqLo, accA, accB)

        float q0, q1;
        #pragma unroll
        for (int m = 0; m < 6; m++) {
            upk2(accA[m], q0, q1);
            if (validA) { slotA[2*m]   = silu_c * q0 * sigf(q0);
                          slotA[2*m+1] = silu_c * q1 * sigf(q1); }
            upk2(accB[m], q0, q1);
            if (validB) { slotB[2*m]   = silu_c * q0 * sigf(q0);
                          slotB[2*m+1] = silu_c * q1 * sigf(q1); }
        }
    }

    // ================= quadratic pass 2: outputs 12-23 =================
    float gA[8], gB[8];
    {
        ull accA[6], accB[6];
        #pragma unroll
        for (int j = 0; j < 6; j++) { accA[j] = 0ull; accB[j] = 0ull; }

        QUAD_PASS(sWqHi, accA, accB)

        float q0, q1;
        #pragma unroll
        for (int m = 0; m < 2; m++) {          // outputs 12-15: scal
            upk2(accA[m], q0, q1);
            if (validA) { slotA[12+2*m] = silu_c * q0 * sigf(q0);
                          slotA[13+2*m] = silu_c * q1 * sigf(q1); }
            upk2(accB[m], q0, q1);
            if (validB) { slotB[12+2*m] = silu_c * q0 * sigf(q0);
                          slotB[13+2*m] = silu_c * q1 * sigf(q1); }
        }
        #pragma unroll
        for (int m = 0; m < 4; m++) {          // outputs 16-23: gates
            upk2(accA[2+m], q0, q1);
            gA[2*m] = sig_c * sigf(q0); gA[2*m+1] = sig_c * sigf(q1);
            upk2(accB[2+m], q0, q1);
            gB[2*m] = sig_c * sigf(q0); gB[2*m+1] = sig_c * sigf(q1);
        }
    }

    // ================= gated bilinear: 4 w-pairs, both rows =================
    #pragma unroll
    for (int wp = 0; wp < 4; wp++) {
        ull AbA[8], AbB[8];
        #pragma unroll
        for (int b = 0; b < 8; b++) { AbA[b] = 0ull; AbB[b] = 0ull; }

        #pragma unroll
        for (int u = 0; u < 16; u++) {
            ull suA = pk2s(sA[u]);
            ull suB = pk2s(sB[u]);
            const ulonglong2* wr = reinterpret_cast<const ulonglong2*>(sWgP + wp * 256 + u * 16);
            ulonglong2 p0 = wr[0];
            AbA[0] = fma2(suA, p0.x, AbA[0]);
            AbA[1] = fma2(suA, p0.y, AbA[1]);
            AbB[0] = fma2(suB, p0.x, AbB[0]);
            AbB[1] = fma2(suB, p0.y, AbB[1]);
            ulonglong2 p1 = wr[1];
            AbA[2] = fma2(suA, p1.x, AbA[2]);
            AbA[3] = fma2(suA, p1.y, AbA[3]);
            AbB[2] = fma2(suB, p1.x, AbB[2]);
            AbB[3] = fma2(suB, p1.y, AbB[3]);
            ulonglong2 p2 = wr[2];
            AbA[4] = fma2(suA, p2.x, AbA[4]);
            AbA[5] = fma2(suA, p2.y, AbA[5]);
            AbB[4] = fma2(suB, p2.x, AbB[4]);
            AbB[5] = fma2(suB, p2.y, AbB[5]);
            ulonglong2 p3 = wr[3];
            AbA[6] = fma2(suA, p3.x, AbA[6]);
            AbA[7] = fma2(suA, p3.y, AbA[7]);
            AbB[6] = fma2(suB, p3.x, AbB[6]);
            AbB[7] = fma2(suB, p3.y, AbB[7]);
        }
        #pragma unroll
        for (int i = 0; i < 3; i++) {
            ull tA = 0ull, tB = 0ull;
            #pragma unroll
            for (int b = 0; b < 8; b++) {
                tA = fma2(AbA[b], pk2s(vA[b*3+i]), tA);
                tB = fma2(AbB[b], pk2s(vB[b*3+i]), tB);
            }
            float lo, hi;
            upk2(tA, lo, hi);
            if (validA) {
                slotA[16 + (2*wp)*3 + i]   = gA[2*wp]   * lo;
                slotA[16 + (2*wp+1)*3 + i] = gA[2*wp+1] * hi;
            }
            upk2(tB, lo, hi);
            if (validB) {
                slotB[16 + (2*wp)*3 + i]   = gB[2*wp]   * lo;
                slotB[16 + (2*wp+1)*3 + i] = gB[2*wp+1] * hi;
            }
        }
    }
    __syncthreads();

    // ---- flush coalesced ----
    float4* gy = reinterpret_cast<float4*>(out + (size_t)base * 40);
    for (int j = tid; j < n4; j += TPB) {
        gy[j] = *reinterpret_cast<const float4*>(&sbuf[(j / 10) * RP + (j % 10) * 4]);
    }
}

// ---------------------------------------------------------------------------
// Host: reproduce reference trapezoid normalization constants (untimed).
// ---------------------------------------------------------------------------
static void compute_constants(double* silu_c, double* sig_c) {
    const int NPT = 200001;
    const double dx = 24.0 / 200000.0;
    const double inv_sqrt2pi = 1.0 / sqrt(2.0 * 3.14159265358979323846);
    double s_silu = 0.0, s_sig = 0.0;
    for (int i = 0; i < NPT; i++) {
        double xv = -12.0 + dx * (double)i;
        double pdf = exp(-0.5 * xv * xv) * inv_sqrt2pi;
        double sg = 1.0 / (1.0 + exp(-xv));
        double si = xv * sg;
        double wgt = (i == 0 || i == NPT - 1) ? 0.5 : 1.0;
        s_silu += wgt * si * si * pdf;
        s_sig  += wgt * sg * sg * pdf;
    }
    s_silu *= dx; s_sig *= dx;
    *silu_c = 1.0 / sqrt(s_silu);
    *sig_c  = 1.0 / sqrt(s_sig);
}

extern "C" void kernel_launch(void* const* d_in, const int* in_sizes, int n_in,
                              void* d_out, int out_size) {
    const float* x    = (const float*)d_in[0];
    const float* Wss0 = (const float*)d_in[1];
    const float* Wvv0 = (const float*)d_in[2];
    const float* Wss1 = (const float*)d_in[3];
    const float* Wvv1 = (const float*)d_in[4];
    const float* Wsv  = (const float*)d_in[5];
    const float* Wvs  = (const float*)d_in[6];
    float* out = (float*)d_out;

    int nrows = in_sizes[0] / 40;

    double sc, gc;
    compute_constants(&sc, &gc);

    prep_kernel<<<1, 256>>>(Wss0, Wvv0, Wss1, Wvv1, Wsv, Wvs);
    int blocks = (nrows + RPB - 1) / RPB;
    seg_kernel<<<blocks, TPB>>>(x, out, nrows, (float)sc, (float)gc);
}

// round 15
// speedup vs baseline: 1.2933x; 1.2933x over previous
#include <cuda_runtime.h>
#include <math.h>

// ---------------------------------------------------------------------------
// SelfExpandingGate: N=500000 rows, 40 floats in/out.
//   Wq[172][24]       : symmetrized quadratic weights (C_SC, 1/sqrt3 folded)
//   WgP[4][16][8][2]  : combined (Wsv+Wvs^T)/16 interleaved by w-pair
// seg_kernel: 64 threads/block, 2 rows/thread (128 rows/block).
//   * coalesced global I/O staged through padded SMEM (row stride 44 floats)
//   * weights broadcast from SMEM, loaded once per 2 rows
//   * all heavy FMAs packed as fp32x2 over output pairs
//   * __launch_bounds__(64, 5): 204-reg ceiling (above natural 171 -> no
//     spill) guaranteeing 5 resident blocks = 10 warps/SM.
// ---------------------------------------------------------------------------

#define NFEAT 172
#define NOUT  24
#define TPB   64
#define RPB   128          // rows per block
#define RP    44           // padded row stride (floats): conflict-free LDS.128

__device__ float g_Wq[NFEAT * NOUT];      // feature-major
__device__ float g_WgP[4 * 16 * 8 * 2];   // [wp][u][b][lane], w = wp*2+lane

typedef unsigned long long ull;

__device__ __forceinline__ ull pk2s(float f) {          // (f, f)
    ull r; asm("mov.b64 %0,{%1,%1};" : "=l"(r) : "f"(f)); return r;
}
__device__ __forceinline__ void upk2(ull v, float& lo, float& hi) {
    asm("mov.b64 {%0,%1},%2;" : "=f"(lo), "=f"(hi) : "l"(v));
}
__device__ __forceinline__ ull fma2(ull a, ull b, ull c) {
    ull d; asm("fma.rn.f32x2 %0,%1,%2,%3;" : "=l"(d) : "l"(a), "l"(b), "l"(c)); return d;
}
__device__ __forceinline__ float sigf(float x) {
    return __fdividef(1.0f, 1.0f + __expf(-x));
}

// ---------------------------------------------------------------------------
// Prep: build combined weights. One block (tiny).
// ---------------------------------------------------------------------------
__global__ void prep_kernel(const float* __restrict__ Wss0,
                            const float* __restrict__ Wvv0,
                            const float* __restrict__ Wss1,
                            const float* __restrict__ Wvv1,
                            const float* __restrict__ Wsv,
                            const float* __restrict__ Wvs) {
    const float CSC  = 0.055901699437494740f;          // 1/sqrt(320)
    const float CSC3 = CSC * 0.57735026918962576f;     // CSC / sqrt(3)
    int tid = threadIdx.x;

    for (int l = tid; l < 136 * 24; l += blockDim.x) {
        int kk = l / 24, j = l % 24;
        int u = 0, r = kk;
        while (r >= 16 - u) { r -= 16 - u; u++; }
        int v = u + r;
        float val;
        if (j < 16) {
            val = Wss0[(u * 16 + v) * 16 + j];
            if (u != v) val += Wss0[(v * 16 + u) * 16 + j];
        } else {
            int w = j - 16;
            val = Wss1[(u * 16 + v) * 8 + w];
            if (u != v) val += Wss1[(v * 16 + u) * 8 + w];
        }
        g_Wq[kk * 24 + j] = val * CSC;
    }
    for (int l = tid; l < 36 * 24; l += blockDim.x) {
        int kk = l / 24, j = l % 24;
        int a = 0, r = kk;
        while (r >= 8 - a) { r -= 8 - a; a++; }
        int b = a + r;
        float val;
        if (j < 16) {
            val = Wvv0[(a * 8 + b) * 16 + j];
            if (a != b) val += Wvv0[(b * 8 + a) * 16 + j];
        } else {
            int w = j - 16;
            val = Wvv1[(a * 8 + b) * 8 + w];
            if (a != b) val += Wvv1[(b * 8 + a) * 8 + w];
        }
        g_Wq[(136 + kk) * 24 + j] = val * CSC3;
    }
    // [wp][u][b][lane], w = wp*2 + lane
    for (int l = tid; l < 4 * 16 * 8 * 2; l += blockDim.x) {
        int lane = l & 1;
        int b = (l >> 1) & 7;
        int u = (l >> 4) & 15;
        int wp = l >> 8;
        int w = wp * 2 + lane;
        g_WgP[l] = (Wsv[(u * 8 + b) * 8 + w] + Wvs[(b * 16 + u) * 8 + w]) * 0.0625f;
    }
}

// ---------------------------------------------------------------------------
// Main kernel.
// ---------------------------------------------------------------------------
__global__ void __launch_bounds__(TPB, 5)
seg_kernel(const float* __restrict__ x, float* __restrict__ out,
           int nrows, float silu_c, float sig_c) {
    __shared__ __align__(16) float sWq[NFEAT * NOUT];       // 16.5 KB
    __shared__ __align__(16) float sWgP[4 * 16 * 8 * 2];    //  4.0 KB
    __shared__ __align__(16) float sbuf[RPB * RP];          // 22.5 KB

    int tid = threadIdx.x;
    for (int i = tid; i < NFEAT * NOUT;   i += TPB) sWq[i]  = g_Wq[i];
    for (int i = tid; i < 4 * 16 * 8 * 2; i += TPB) sWgP[i] = g_WgP[i];

    int base = blockIdx.x * RPB;
    int rows = nrows - base; if (rows > RPB) rows = RPB;
    int n4 = rows * 10;                   // float4 chunks this block

    // ---- cooperative coalesced load into padded SMEM ----
    const float4* gx = reinterpret_cast<const float4*>(x + (size_t)base * 40);
    for (int j = tid; j < n4; j += TPB) {
        float4 t = gx[j];
        int r = j / 10, c = (j % 10) * 4;
        *reinterpret_cast<float4*>(&sbuf[r * RP + c]) = t;
    }
    __syncthreads();

    // ---- pull this thread's 2 rows into registers (conflict-free LDS.128) ----
    float sA[16], vA[24], sB[16], vB[24];
    {
        const float4* rA = reinterpret_cast<const float4*>(&sbuf[tid * RP]);
        const float4* rB = reinterpret_cast<const float4*>(&sbuf[(tid + TPB) * RP]);
        float4 t;
        t = rA[0]; sA[0]=t.x; sA[1]=t.y; sA[2]=t.z; sA[3]=t.w;
        t = rA[1]; sA[4]=t.x; sA[5]=t.y; sA[6]=t.z; sA[7]=t.w;
        t = rA[2]; sA[8]=t.x; sA[9]=t.y; sA[10]=t.z; sA[11]=t.w;
        t = rA[3]; sA[12]=t.x; sA[13]=t.y; sA[14]=t.z; sA[15]=t.w;
        t = rA[4]; vA[0]=t.x; vA[1]=t.y; vA[2]=t.z; vA[3]=t.w;
        t = rA[5]; vA[4]=t.x; vA[5]=t.y; vA[6]=t.z; vA[7]=t.w;
        t = rA[6]; vA[8]=t.x; vA[9]=t.y; vA[10]=t.z; vA[11]=t.w;
        t = rA[7]; vA[12]=t.x; vA[13]=t.y; vA[14]=t.z; vA[15]=t.w;
        t = rA[8]; vA[16]=t.x; vA[17]=t.y; vA[18]=t.z; vA[19]=t.w;
        t = rA[9]; vA[20]=t.x; vA[21]=t.y; vA[22]=t.z; vA[23]=t.w;
        t = rB[0]; sB[0]=t.x; sB[1]=t.y; sB[2]=t.z; sB[3]=t.w;
        t = rB[1]; sB[4]=t.x; sB[5]=t.y; sB[6]=t.z; sB[7]=t.w;
        t = rB[2]; sB[8]=t.x; sB[9]=t.y; sB[10]=t.z; sB[11]=t.w;
        t = rB[3]; sB[12]=t.x; sB[13]=t.y; sB[14]=t.z; sB[15]=t.w;
        t = rB[4]; vB[0]=t.x; vB[1]=t.y; vB[2]=t.z; vB[3]=t.w;
        t = rB[5]; vB[4]=t.x; vB[5]=t.y; vB[6]=t.z; vB[7]=t.w;
        t = rB[6]; vB[8]=t.x; vB[9]=t.y; vB[10]=t.z; vB[11]=t.w;
        t = rB[7]; vB[12]=t.x; vB[13]=t.y; vB[14]=t.z; vB[15]=t.w;
        t = rB[8]; vB[16]=t.x; vB[17]=t.y; vB[18]=t.z; vB[19]=t.w;
        t = rB[9]; vB[20]=t.x; vB[21]=t.y; vB[22]=t.z; vB[23]=t.w;
    }

    // ---- quadratic contraction: 172 features -> 24 outputs (12 f32x2 accs/row) ----
    ull accA[12], accB[12];
    #pragma unroll
    for (int j = 0; j < 12; j++) { accA[j] = 0ull; accB[j] = 0ull; }

    {
        int k = 0;
        #pragma unroll
        for (int u = 0; u < 16; u++) {
            #pragma unroll
            for (int vv = u; vv < 16; vv++) {
                ull fA2 = pk2s(sA[u] * sA[vv]);
                ull fB2 = pk2s(sB[u] * sB[vv]);
                const ulonglong2* w = reinterpret_cast<const ulonglong2*>(sWq + k * 24);
                #pragma unroll
                for (int j = 0; j < 6; j++) {
                    ulonglong2 wq = w[j];
                    accA[2*j]   = fma2(fA2, wq.x, accA[2*j]);
                    accA[2*j+1] = fma2(fA2, wq.y, accA[2*j+1]);
                    accB[2*j]   = fma2(fB2, wq.x, accB[2*j]);
                    accB[2*j+1] = fma2(fB2, wq.y, accB[2*j+1]);
                }
                k++;
            }
        }
        #pragma unroll
        for (int a = 0; a < 8; a++) {
            #pragma unroll
            for (int b = a; b < 8; b++) {
                float fA = vA[a*3+0]*vA[b*3+0] + vA[a*3+1]*vA[b*3+1]
                         + vA[a*3+2]*vA[b*3+2];
                float fB = vB[a*3+0]*vB[b*3+0] + vB[a*3+1]*vB[b*3+1]
                         + vB[a*3+2]*vB[b*3+2];
                ull fA2 = pk2s(fA);
                ull fB2 = pk2s(fB);
                const ulonglong2* w = reinterpret_cast<const ulonglong2*>(sWq + k * 24);
                #pragma unroll
                for (int j = 0; j < 6; j++) {
                    ulonglong2 wq = w[j];
                    accA[2*j]   = fma2(fA2, wq.x, accA[2*j]);
                    accA[2*j+1] = fma2(fA2, wq.y, accA[2*j+1]);
                    accB[2*j]   = fma2(fB2, wq.x, accB[2*j]);
                    accB[2*j+1] = fma2(fB2, wq.y, accB[2*j+1]);
                }
                k++;
            }
        }
    }

    // ---- epilogue 1: out_s to SMEM rows, compute gates ----
    float gA[8], gB[8];
    {
        float q0, q1;
        float* oA = &sbuf[tid * RP];
        float* oB = &sbuf[(tid + TPB) * RP];
        #pragma unroll
        for (int m = 0; m < 8; m++) {          // acc pairs 0..7 -> 16 scal outs
            upk2(accA[m], q0, q1);
            oA[2*m]   = silu_c * q0 * sigf(q0);
            oA[2*m+1] = silu_c * q1 * sigf(q1);
            upk2(accB[m], q0, q1);
            oB[2*m]   = silu_c * q0 * sigf(q0);
            oB[2*m+1] = silu_c * q1 * sigf(q1);
        }
        #pragma unroll
        for (int m = 0; m < 4; m++) {          // acc pairs 8..11 -> 8 gates
            upk2(accA[8+m], q0, q1);
            gA[2*m] = sig_c * sigf(q0); gA[2*m+1] = sig_c * sigf(q1);
            upk2(accB[8+m], q0, q1);
            gB[2*m] = sig_c * sigf(q0); gB[2*m+1] = sig_c * sigf(q1);
        }
    }

    // ---- gated bilinear, per w-pair, both rows together ----
    // gated[w,i] = sum_b ( sum_u s_u WgP[wp,u,b,(w&1)] ) * v[b,i]
    {
        float* oA = &sbuf[tid * RP + 16];
        float* oB = &sbuf[(tid + TPB) * RP + 16];
        #pragma unroll
        for (int wp = 0; wp < 4; wp++) {
            ull AbA[8], AbB[8];
            #pragma unroll
            for (int b = 0; b < 8; b++) { AbA[b] = 0ull; AbB[b] = 0ull; }

            #pragma unroll
            for (int u = 0; u < 16; u++) {
                ull suA = pk2s(sA[u]);
                ull suB = pk2s(sB[u]);
                const ulonglong2* wr =
                    reinterpret_cast<const ulonglong2*>(sWgP + wp * 256 + u * 16);
                #pragma unroll
                for (int m = 0; m < 4; m++) {
                    ulonglong2 p = wr[m];
                    AbA[2*m]   = fma2(suA, p.x, AbA[2*m]);
                    AbA[2*m+1] = fma2(suA, p.y, AbA[2*m+1]);
                    AbB[2*m]   = fma2(suB, p.x, AbB[2*m]);
                    AbB[2*m+1] = fma2(suB, p.y, AbB[2*m+1]);
                }
            }
            #pragma unroll
            for (int i = 0; i < 3; i++) {
                ull tA = 0ull, tB = 0ull;
                #pragma unroll
                for (int b = 0; b < 8; b++) {
                    tA = fma2(AbA[b], pk2s(vA[b*3+i]), tA);
                    tB = fma2(AbB[b], pk2s(vB[b*3+i]), tB);
                }
                float lo, hi;
                upk2(tA, lo, hi);
                oA[(2*wp)*3 + i]   = gA[2*wp]   * lo;
                oA[(2*wp+1)*3 + i] = gA[2*wp+1] * hi;
                upk2(tB, lo, hi);
                oB[(2*wp)*3 + i]   = gB[2*wp]   * lo;
                oB[(2*wp+1)*3 + i] = gB[2*wp+1] * hi;
            }
        }
    }

    __syncthreads();

    // ---- cooperative coalesced store ----
    float4* gy = reinterpret_cast<float4*>(out + (size_t)base * 40);
    for (int j = tid; j < n4; j += TPB) {
        int r = j / 10, c = (j % 10) * 4;
        gy[j] = *reinterpret_cast<const float4*>(&sbuf[r * RP + c]);
    }
}

// ---------------------------------------------------------------------------
// Host: reproduce reference trapezoid normalization constants (untimed).
// ---------------------------------------------------------------------------
static void compute_constants(double* silu_c, double* sig_c) {
    const int NPT = 200001;
    const double dx = 24.0 / 200000.0;
    const double inv_sqrt2pi = 1.0 / sqrt(2.0 * 3.14159265358979323846);
    double s_silu = 0.0, s_sig = 0.0;
    for (int i = 0; i < NPT; i++) {
        double xv = -12.0 + dx * (double)i;
        double pdf = exp(-0.5 * xv * xv) * inv_sqrt2pi;
        double sg = 1.0 / (1.0 + exp(-xv));
        double si = xv * sg;
        double wgt = (i == 0 || i == NPT - 1) ? 0.5 : 1.0;
        s_silu += wgt * si * si * pdf;
        s_sig  += wgt * sg * sg * pdf;
    }
    s_silu *= dx; s_sig *= dx;
    *silu_c = 1.0 / sqrt(s_silu);
    *sig_c  = 1.0 / sqrt(s_sig);
}

extern "C" void kernel_launch(void* const* d_in, const int* in_sizes, int n_in,
                              void* d_out, int out_size) {
    const float* x    = (const float*)d_in[0];
    const float* Wss0 = (const float*)d_in[1];
    const float* Wvv0 = (const float*)d_in[2];
    const float* Wss1 = (const float*)d_in[3];
    const float* Wvv1 = (const float*)d_in[4];
    const float* Wsv  = (const float*)d_in[5];
    const float* Wvs  = (const float*)d_in[6];
    float* out = (float*)d_out;

    int nrows = in_sizes[0] / 40;

    double sc, gc;
    compute_constants(&sc, &gc);

    prep_kernel<<<1, 256>>>(Wss0, Wvv0, Wss1, Wvv1, Wsv, Wvs);
    int blocks = (nrows + RPB - 1) / RPB;
    seg_kernel<<<blocks, TPB>>>(x, out, nrows, (float)sc, (float)gc);
}

// round 16
// speedup vs baseline: 1.3144x; 1.0163x over previous
#include <cuda_runtime.h>
#include <math.h>

// ---------------------------------------------------------------------------
// SelfExpandingGate: N=500000 rows, 40 floats in/out.
//   Wq[172][24]       : symmetrized quadratic weights (C_SC, 1/sqrt3 folded)
//   WgP[4][16][8][2]  : combined (Wsv+Wvs^T)/16 interleaved by w-pair
// seg_kernel: 64 threads/block, 2 rows/thread (128 rows/block).
//   * I/O staged through a HALF-SIZE (64-slot) SMEM buffer in two chunks so
//     smem/block = 33.1 KB -> 6 resident blocks = 12 warps/SM (the register-
//     file maximum at ~170 regs).
//   * weights broadcast from SMEM, loaded once per 2 rows
//   * all heavy FMAs packed as fp32x2 over output pairs
//   * __launch_bounds__(64, 6): 170-reg ceiling, just above natural 168.
// ---------------------------------------------------------------------------

#define NFEAT 172
#define NOUT  24
#define TPB   64
#define RPB   128          // rows per block (2 chunks of 64)
#define RP    52           // slot stride (floats): 208B, 16B-aligned
#define NSLOT 64

__device__ float g_Wq[NFEAT * NOUT];      // feature-major
__device__ float g_WgP[4 * 16 * 8 * 2];   // [wp][u][b][lane], w = wp*2+lane

typedef unsigned long long ull;

__device__ __forceinline__ ull pk2s(float f) {          // (f, f)
    ull r; asm("mov.b64 %0,{%1,%1};" : "=l"(r) : "f"(f)); return r;
}
__device__ __forceinline__ void upk2(ull v, float& lo, float& hi) {
    asm("mov.b64 {%0,%1},%2;" : "=f"(lo), "=f"(hi) : "l"(v));
}
__device__ __forceinline__ ull fma2(ull a, ull b, ull c) {
    ull d; asm("fma.rn.f32x2 %0,%1,%2,%3;" : "=l"(d) : "l"(a), "l"(b), "l"(c)); return d;
}
__device__ __forceinline__ float sigf(float x) {
    return __fdividef(1.0f, 1.0f + __expf(-x));
}

// ---------------------------------------------------------------------------
// Prep: build combined weights. One block (tiny).
// ---------------------------------------------------------------------------
__global__ void prep_kernel(const float* __restrict__ Wss0,
                            const float* __restrict__ Wvv0,
                            const float* __restrict__ Wss1,
                            const float* __restrict__ Wvv1,
                            const float* __restrict__ Wsv,
                            const float* __restrict__ Wvs) {
    const float CSC  = 0.055901699437494740f;          // 1/sqrt(320)
    const float CSC3 = CSC * 0.57735026918962576f;     // CSC / sqrt(3)
    int tid = threadIdx.x;

    for (int l = tid; l < 136 * 24; l += blockDim.x) {
        int kk = l / 24, j = l % 24;
        int u = 0, r = kk;
        while (r >= 16 - u) { r -= 16 - u; u++; }
        int v = u + r;
        float val;
        if (j < 16) {
            val = Wss0[(u * 16 + v) * 16 + j];
            if (u != v) val += Wss0[(v * 16 + u) * 16 + j];
        } else {
            int w = j - 16;
            val = Wss1[(u * 16 + v) * 8 + w];
            if (u != v) val += Wss1[(v * 16 + u) * 8 + w];
        }
        g_Wq[kk * 24 + j] = val * CSC;
    }
    for (int l = tid; l < 36 * 24; l += blockDim.x) {
        int kk = l / 24, j = l % 24;
        int a = 0, r = kk;
        while (r >= 8 - a) { r -= 8 - a; a++; }
        int b = a + r;
        float val;
        if (j < 16) {
            val = Wvv0[(a * 8 + b) * 16 + j];
            if (a != b) val += Wvv0[(b * 8 + a) * 16 + j];
        } else {
            int w = j - 16;
            val = Wvv1[(a * 8 + b) * 8 + w];
            if (a != b) val += Wvv1[(b * 8 + a) * 8 + w];
        }
        g_Wq[(136 + kk) * 24 + j] = val * CSC3;
    }
    // [wp][u][b][lane], w = wp*2 + lane
    for (int l = tid; l < 4 * 16 * 8 * 2; l += blockDim.x) {
        int lane = l & 1;
        int b = (l >> 1) & 7;
        int u = (l >> 4) & 15;
        int wp = l >> 8;
        int w = wp * 2 + lane;
        g_WgP[l] = (Wsv[(u * 8 + b) * 8 + w] + Wvs[(b * 16 + u) * 8 + w]) * 0.0625f;
    }
}

// ---------------------------------------------------------------------------
// Main kernel.
// ---------------------------------------------------------------------------
__global__ void __launch_bounds__(TPB, 6)
seg_kernel(const float* __restrict__ x, float* __restrict__ out,
           int nrows, float silu_c, float sig_c) {
    __shared__ __align__(16) float sWq[NFEAT * NOUT];       // 16.5 KB
    __shared__ __align__(16) float sWgP[4 * 16 * 8 * 2];    //  4.0 KB
    __shared__ __align__(16) float sbuf[NSLOT * RP];        // 13.0 KB

    int tid = threadIdx.x;
    for (int i = tid; i < NFEAT * NOUT;   i += TPB) sWq[i]  = g_Wq[i];
    for (int i = tid; i < 4 * 16 * 8 * 2; i += TPB) sWgP[i] = g_WgP[i];

    const int base = blockIdx.x * RPB;
    int rem = nrows - base;
    const int rows1 = rem > TPB ? TPB : (rem > 0 ? rem : 0);
    rem -= TPB;
    const int rows2 = rem > TPB ? TPB : (rem > 0 ? rem : 0);

    float* slot = &sbuf[tid * RP];

    // ---- chunk 1: stage + extract row A ----
    {
        const float4* gx = reinterpret_cast<const float4*>(x + (size_t)base * 40);
        for (int j = tid; j < rows1 * 10; j += TPB) {
            float4 t = gx[j];
            *reinterpret_cast<float4*>(&sbuf[(j / 10) * RP + (j % 10) * 4]) = t;
        }
    }
    __syncthreads();
    float sA[16], vA[24], sB[16], vB[24];
    {
        const float4* r4 = reinterpret_cast<const float4*>(slot);
        float4 t;
        t = r4[0]; sA[0]=t.x; sA[1]=t.y; sA[2]=t.z; sA[3]=t.w;
        t = r4[1]; sA[4]=t.x; sA[5]=t.y; sA[6]=t.z; sA[7]=t.w;
        t = r4[2]; sA[8]=t.x; sA[9]=t.y; sA[10]=t.z; sA[11]=t.w;
        t = r4[3]; sA[12]=t.x; sA[13]=t.y; sA[14]=t.z; sA[15]=t.w;
        t = r4[4]; vA[0]=t.x; vA[1]=t.y; vA[2]=t.z; vA[3]=t.w;
        t = r4[5]; vA[4]=t.x; vA[5]=t.y; vA[6]=t.z; vA[7]=t.w;
        t = r4[6]; vA[8]=t.x; vA[9]=t.y; vA[10]=t.z; vA[11]=t.w;
        t = r4[7]; vA[12]=t.x; vA[13]=t.y; vA[14]=t.z; vA[15]=t.w;
        t = r4[8]; vA[16]=t.x; vA[17]=t.y; vA[18]=t.z; vA[19]=t.w;
        t = r4[9]; vA[20]=t.x; vA[21]=t.y; vA[22]=t.z; vA[23]=t.w;
    }
    __syncthreads();
    // ---- chunk 2: stage + extract row B ----
    {
        const float4* gx = reinterpret_cast<const float4*>(x + (size_t)(base + TPB) * 40);
        for (int j = tid; j < rows2 * 10; j += TPB) {
            float4 t = gx[j];
            *reinterpret_cast<float4*>(&sbuf[(j / 10) * RP + (j % 10) * 4]) = t;
        }
    }
    __syncthreads();
    {
        const float4* r4 = reinterpret_cast<const float4*>(slot);
        float4 t;
        t = r4[0]; sB[0]=t.x; sB[1]=t.y; sB[2]=t.z; sB[3]=t.w;
        t = r4[1]; sB[4]=t.x; sB[5]=t.y; sB[6]=t.z; sB[7]=t.w;
        t = r4[2]; sB[8]=t.x; sB[9]=t.y; sB[10]=t.z; sB[11]=t.w;
        t = r4[3]; sB[12]=t.x; sB[13]=t.y; sB[14]=t.z; sB[15]=t.w;
        t = r4[4]; vB[0]=t.x; vB[1]=t.y; vB[2]=t.z; vB[3]=t.w;
        t = r4[5]; vB[4]=t.x; vB[5]=t.y; vB[6]=t.z; vB[7]=t.w;
        t = r4[6]; vB[8]=t.x; vB[9]=t.y; vB[10]=t.z; vB[11]=t.w;
        t = r4[7]; vB[12]=t.x; vB[13]=t.y; vB[14]=t.z; vB[15]=t.w;
        t = r4[8]; vB[16]=t.x; vB[17]=t.y; vB[18]=t.z; vB[19]=t.w;
        t = r4[9]; vB[20]=t.x; vB[21]=t.y; vB[22]=t.z; vB[23]=t.w;
    }
    __syncthreads();    // inputs consumed; sbuf reusable for outputs

    // ---- quadratic contraction: 172 features -> 24 outputs (12 f32x2 accs/row) ----
    ull accA[12], accB[12];
    #pragma unroll
    for (int j = 0; j < 12; j++) { accA[j] = 0ull; accB[j] = 0ull; }

    {
        int k = 0;
        #pragma unroll
        for (int u = 0; u < 16; u++) {
            #pragma unroll
            for (int vv = u; vv < 16; vv++) {
                ull fA2 = pk2s(sA[u] * sA[vv]);
                ull fB2 = pk2s(sB[u] * sB[vv]);
                const ulonglong2* w = reinterpret_cast<const ulonglong2*>(sWq + k * 24);
                #pragma unroll
                for (int j = 0; j < 6; j++) {
                    ulonglong2 wq = w[j];
                    accA[2*j]   = fma2(fA2, wq.x, accA[2*j]);
                    accA[2*j+1] = fma2(fA2, wq.y, accA[2*j+1]);
                    accB[2*j]   = fma2(fB2, wq.x, accB[2*j]);
                    accB[2*j+1] = fma2(fB2, wq.y, accB[2*j+1]);
                }
                k++;
            }
        }
        #pragma unroll
        for (int a = 0; a < 8; a++) {
            #pragma unroll
            for (int b = a; b < 8; b++) {
                float fA = vA[a*3+0]*vA[b*3+0] + vA[a*3+1]*vA[b*3+1]
                         + vA[a*3+2]*vA[b*3+2];
                float fB = vB[a*3+0]*vB[b*3+0] + vB[a*3+1]*vB[b*3+1]
                         + vB[a*3+2]*vB[b*3+2];
                ull fA2 = pk2s(fA);
                ull fB2 = pk2s(fB);
                const ulonglong2* w = reinterpret_cast<const ulonglong2*>(sWq + k * 24);
                #pragma unroll
                for (int j = 0; j < 6; j++) {
                    ulonglong2 wq = w[j];
                    accA[2*j]   = fma2(fA2, wq.x, accA[2*j]);
                    accA[2*j+1] = fma2(fA2, wq.y, accA[2*j+1]);
                    accB[2*j]   = fma2(fB2, wq.x, accB[2*j]);
                    accB[2*j+1] = fma2(fB2, wq.y, accB[2*j+1]);
                }
                k++;
            }
        }
    }

    // ---- epilogue 1: scal outs staged (A -> slot[0..16), B -> slot[16..32)) ----
    float gA[8], gB[8];
    {
        float q0, q1;
        #pragma unroll
        for (int m = 0; m < 8; m++) {          // acc pairs 0..7 -> 16 scal outs
            upk2(accA[m], q0, q1);
            slot[2*m]    = silu_c * q0 * sigf(q0);
            slot[2*m+1]  = silu_c * q1 * sigf(q1);
            upk2(accB[m], q0, q1);
            slot[16+2*m] = silu_c * q0 * sigf(q0);
            slot[17+2*m] = silu_c * q1 * sigf(q1);
        }
        #pragma unroll
        for (int m = 0; m < 4; m++) {          // acc pairs 8..11 -> 8 gates
            upk2(accA[8+m], q0, q1);
            gA[2*m] = sig_c * sigf(q0); gA[2*m+1] = sig_c * sigf(q1);
            upk2(accB[8+m], q0, q1);
            gB[2*m] = sig_c * sigf(q0); gB[2*m+1] = sig_c * sigf(q1);
        }
    }
    __syncthreads();

    // ---- flush scal outputs for both chunks ----
    {
        for (int j = tid; j < rows1 * 4; j += TPB) {
            int r = j >> 2, c = (j & 3) * 4;
            *reinterpret_cast<float4*>(out + (size_t)(base + r) * 40 + c) =
                *reinterpret_cast<const float4*>(&sbuf[r * RP + c]);
        }
        for (int j = tid; j < rows2 * 4; j += TPB) {
            int r = j >> 2, c = (j & 3) * 4;
            *reinterpret_cast<float4*>(out + (size_t)(base + TPB + r) * 40 + c) =
                *reinterpret_cast<const float4*>(&sbuf[r * RP + 16 + c]);
        }
    }
    __syncthreads();

    // ---- gated bilinear, per w-pair, both rows together ----
    // gated[w,i] = sum_b ( sum_u s_u WgP[wp,u,b,(w&1)] ) * v[b,i]
    // A ov -> slot[0..24), B ov -> slot[24..48)
    {
        #pragma unroll
        for (int wp = 0; wp < 4; wp++) {
            ull AbA[8], AbB[8];
            #pragma unroll
            for (int b = 0; b < 8; b++) { AbA[b] = 0ull; AbB[b] = 0ull; }

            #pragma unroll
            for (int u = 0; u < 16; u++) {
                ull suA = pk2s(sA[u]);
                ull suB = pk2s(sB[u]);
                const ulonglong2* wr =
                    reinterpret_cast<const ulonglong2*>(sWgP + wp * 256 + u * 16);
                #pragma unroll
                for (int m = 0; m < 4; m++) {
                    ulonglong2 p = wr[m];
                    AbA[2*m]   = fma2(suA, p.x, AbA[2*m]);
                    AbA[2*m+1] = fma2(suA, p.y, AbA[2*m+1]);
                    AbB[2*m]   = fma2(suB, p.x, AbB[2*m]);
                    AbB[2*m+1] = fma2(suB, p.y, AbB[2*m+1]);
                }
            }
            #pragma unroll
            for (int i = 0; i < 3; i++) {
                ull tA = 0ull, tB = 0ull;
                #pragma unroll
                for (int b = 0; b < 8; b++) {
                    tA = fma2(AbA[b], pk2s(vA[b*3+i]), tA);
                    tB = fma2(AbB[b], pk2s(vB[b*3+i]), tB);
                }
                float lo, hi;
                upk2(tA, lo, hi);
                slot[(2*wp)*3 + i]        = gA[2*wp]   * lo;
                slot[(2*wp+1)*3 + i]      = gA[2*wp+1] * hi;
                upk2(tB, lo, hi);
                slot[24 + (2*wp)*3 + i]   = gB[2*wp]   * lo;
                slot[24 + (2*wp+1)*3 + i] = gB[2*wp+1] * hi;
            }
        }
    }
    __syncthreads();

    // ---- flush vector outputs for both chunks ----
    {
        for (int j = tid; j < rows1 * 6; j += TPB) {
            int r = j / 6, c = (j % 6) * 4;
            *reinterpret_cast<float4*>(out + (size_t)(base + r) * 40 + 16 + c) =
                *reinterpret_cast<const float4*>(&sbuf[r * RP + c]);
        }
        for (int j = tid; j < rows2 * 6; j += TPB) {
            int r = j / 6, c = (j % 6) * 4;
            *reinterpret_cast<float4*>(out + (size_t)(base + TPB + r) * 40 + 16 + c) =
                *reinterpret_cast<const float4*>(&sbuf[r * RP + 24 + c]);
        }
    }
}

// ---------------------------------------------------------------------------
// Host: reproduce reference trapezoid normalization constants (untimed).
// ---------------------------------------------------------------------------
static void compute_constants(double* silu_c, double* sig_c) {
    const int NPT = 200001;
    const double dx = 24.0 / 200000.0;
    const double inv_sqrt2pi = 1.0 / sqrt(2.0 * 3.14159265358979323846);
    double s_silu = 0.0, s_sig = 0.0;
    for (int i = 0; i < NPT; i++) {
        double xv = -12.0 + dx * (double)i;
        double pdf = exp(-0.5 * xv * xv) * inv_sqrt2pi;
        double sg = 1.0 / (1.0 + exp(-xv));
        double si = xv * sg;
        double wgt = (i == 0 || i == NPT - 1) ? 0.5 : 1.0;
        s_silu += wgt * si * si * pdf;
        s_sig  += wgt * sg * sg * pdf;
    }
    s_silu *= dx; s_sig *= dx;
    *silu_c = 1.0 / sqrt(s_silu);
    *sig_c  = 1.0 / sqrt(s_sig);
}

extern "C" void kernel_launch(void* const* d_in, const int* in_sizes, int n_in,
                              void* d_out, int out_size) {
    const float* x    = (const float*)d_in[0];
    const float* Wss0 = (const float*)d_in[1];
    const float* Wvv0 = (const float*)d_in[2];
    const float* Wss1 = (const float*)d_in[3];
    const float* Wvv1 = (const float*)d_in[4];
    const float* Wsv  = (const float*)d_in[5];
    const float* Wvs  = (const float*)d_in[6];
    float* out = (float*)d_out;

    int nrows = in_sizes[0] / 40;

    double sc, gc;
    compute_constants(&sc, &gc);

    prep_kernel<<<1, 256>>>(Wss0, Wvv0, Wss1, Wvv1, Wsv, Wvs);
    int blocks = (nrows + RPB - 1) / RPB;
    seg_kernel<<<blocks, TPB>>>(x, out, nrows, (float)sc, (float)gc);
}